// round 12
// baseline (speedup 1.0000x reference)
#include <cuda_runtime.h>
#include <cuda_bf16.h>

#define NNODE 128
#define NM1   127            // edges per receiver
#define NRR   (NNODE * NM1)  // 16256 directed edges
#define BB    128
#define CC    16
#define BPC   2              // batches per CTA (b and b + BB/2)
#define F4_PER_R (NM1 * 4)   // 508 float4s per (b, r) chunk
#define B_STRIDE 8192        // smem bytes per batch region (8128 + pad)

// SW128 swizzle: XOR bits [9:7] into [6:4]. Batch regions are 8192B-aligned
// so the swizzle composes with the region offset. Verified conflict-free for
// both phase-1 (8 consecutive float4s/row) and phase-2 (stride-4 column).
__device__ __forceinline__ unsigned swz(unsigned byte_off) {
    return byte_off ^ ((byte_off >> 3) & 0x70u);
}

// One CTA per (receiver r, batch pair {b, b+64}). 128 threads. R8 structure,
// doubled along the batch axis for ILP/MLP:
//
// Phase 1: f = t + 128j over 508 float4s, BOTH batches loaded back-to-back
//          (8 front-batched LDG.128 -> MLP 8); exp accumulated straight from
//          load registers into two independent float4 accs; raw x staged into
//          two swizzled smem regions for the phase-2 transpose.
// Reduce:  3-stage xor-shuffle (masks 4,8,16; lanes sharing quad q = t&3)
//          per stream; 4-warp combine via smem; 32 threads -> one __frcp_rn
//          per (batch, channel).
// Phase 2: thread t = edge t; per batch 4 conflict-free LDS.128, scale,
//          16 warp-coalesced STG.32 (128B runs per channel).
__global__ __launch_bounds__(128) void attention2_denom_kernel(
    const float* __restrict__ x, float* __restrict__ out)
{
    const int r    = blockIdx.x;
    const int b0   = blockIdx.y;          // batches b0 and b0 + BB/2
    const int t    = threadIdx.x;
    const int warp = t >> 5;
    const int lane = t & 31;

    __shared__ __align__(16) unsigned char v_s[BPC * B_STRIDE]; // 16KB staged x
    __shared__ float4 ws4[4][BPC][4];     // [warp][batch][quad]
    __shared__ float4 rden4[BPC][4];      // reciprocals per batch

    const float4* __restrict__ src0 = reinterpret_cast<const float4*>(
        x + ((size_t)b0 * NRR + (size_t)r * NM1) * CC);
    const float4* __restrict__ src1 = reinterpret_cast<const float4*>(
        x + ((size_t)(b0 + BB / 2) * NRR + (size_t)r * NM1) * CC);

    // ---- Phase 1: coalesced streaming loads; exp from registers; stage -----
    float4 acc0 = make_float4(0.f, 0.f, 0.f, 0.f);
    float4 acc1 = make_float4(0.f, 0.f, 0.f, 0.f);
    #pragma unroll
    for (int j = 0; j < 4; j++) {
        int f = t + 128 * j;                       // [0, 512)
        if (f < F4_PER_R) {                        // j=3 predicated (t < 124)
            float4 g0 = __ldcs(src0 + f);
            float4 g1 = __ldcs(src1 + f);
            acc0.x += __expf(g0.x);  acc0.y += __expf(g0.y);
            acc0.z += __expf(g0.z);  acc0.w += __expf(g0.w);
            acc1.x += __expf(g1.x);  acc1.y += __expf(g1.y);
            acc1.z += __expf(g1.z);  acc1.w += __expf(g1.w);
            unsigned off = swz(16u * (unsigned)f);
            *reinterpret_cast<float4*>(v_s + off)            = g0;
            *reinterpret_cast<float4*>(v_s + B_STRIDE + off) = g1;
        }
    }

    // Lanes sharing channel-quad q = t&3 differ in bits {2,3,4}.
    #pragma unroll
    for (int m = 4; m <= 16; m <<= 1) {
        acc0.x += __shfl_xor_sync(0xffffffffu, acc0.x, m);
        acc0.y += __shfl_xor_sync(0xffffffffu, acc0.y, m);
        acc0.z += __shfl_xor_sync(0xffffffffu, acc0.z, m);
        acc0.w += __shfl_xor_sync(0xffffffffu, acc0.w, m);
        acc1.x += __shfl_xor_sync(0xffffffffu, acc1.x, m);
        acc1.y += __shfl_xor_sync(0xffffffffu, acc1.y, m);
        acc1.z += __shfl_xor_sync(0xffffffffu, acc1.z, m);
        acc1.w += __shfl_xor_sync(0xffffffffu, acc1.w, m);
    }
    if (lane < 4) {                        // lane == its quad q
        ws4[warp][0][lane] = acc0;
        ws4[warp][1][lane] = acc1;
    }
    __syncthreads();

    if (t < BPC * CC) {                    // 32 threads: one (batch, channel)
        const int g = t >> 4;
        const int c = t & 15;
        float d = 0.f;
        #pragma unroll
        for (int w = 0; w < 4; w++)
            d += reinterpret_cast<const float*>(ws4[w][g])[c];
        reinterpret_cast<float*>(rden4[g])[c] = __frcp_rn(d);
    }
    __syncthreads();

    // ---- Phase 2: edge-owned readback + coalesced transposed stores --------
    if (t < NM1) {
        #pragma unroll
        for (int g = 0; g < BPC; g++) {
            const unsigned char* base = v_s + g * B_STRIDE;
            float4 rd0 = rden4[g][0], rd1 = rden4[g][1];
            float4 rd2 = rden4[g][2], rd3 = rden4[g][3];
            float4 v0 = *reinterpret_cast<const float4*>(base + swz(16u * (4u * t + 0)));
            float4 v1 = *reinterpret_cast<const float4*>(base + swz(16u * (4u * t + 1)));
            float4 v2 = *reinterpret_cast<const float4*>(base + swz(16u * (4u * t + 2)));
            float4 v3 = *reinterpret_cast<const float4*>(base + swz(16u * (4u * t + 3)));

            float* o = out + (size_t)(b0 + g * (BB / 2)) * CC * NRR
                           + (size_t)r * NM1 + (size_t)t;
            o[ 0 * NRR] = v0.x * rd0.x;  o[ 1 * NRR] = v0.y * rd0.y;
            o[ 2 * NRR] = v0.z * rd0.z;  o[ 3 * NRR] = v0.w * rd0.w;
            o[ 4 * NRR] = v1.x * rd1.x;  o[ 5 * NRR] = v1.y * rd1.y;
            o[ 6 * NRR] = v1.z * rd1.z;  o[ 7 * NRR] = v1.w * rd1.w;
            o[ 8 * NRR] = v2.x * rd2.x;  o[ 9 * NRR] = v2.y * rd2.y;
            o[10 * NRR] = v2.z * rd2.z;  o[11 * NRR] = v2.w * rd2.w;
            o[12 * NRR] = v3.x * rd3.x;  o[13 * NRR] = v3.y * rd3.y;
            o[14 * NRR] = v3.z * rd3.z;  o[15 * NRR] = v3.w * rd3.w;
        }
    }
}

extern "C" void kernel_launch(void* const* d_in, const int* in_sizes, int n_in,
                              void* d_out, int out_size)
{
    // d_in[0]: x  float32 [B, NR, C]
    // d_in[1]: receivers int32 [NR] — structurally i/(N-1), unused
    const float* x   = (const float*)d_in[0];
    float*       out = (float*)d_out;   // float32 [B, C, NR]

    dim3 grid(NNODE, BB / BPC);   // (receiver, batch-pair)
    attention2_denom_kernel<<<grid, 128>>>(x, out);
}

// round 13
// speedup vs baseline: 1.3287x; 1.3287x over previous
#include <cuda_runtime.h>
#include <cuda_bf16.h>

#define NNODE 128
#define NM1   127            // edges per receiver
#define NRR   (NNODE * NM1)  // 16256 directed edges
#define BB    128
#define CC    16

// SW128-style smem swizzle on byte offsets: XOR bits [9:7] into [6:4].
// Conflict-free for both phase-1 writes (8 consecutive float4s per row) and
// phase-2 reads (stride-4 float4 column).
__device__ __forceinline__ unsigned swz(unsigned byte_off) {
    return byte_off ^ ((byte_off >> 3) & 0x70u);
}

// One CTA per (batch b, receiver r), 128 threads.  [R8 structure + .cs hints]
//
// Phase 1 (scrambled ownership, perfectly coalesced loads):
//   thread t loads float4 #(t + 128j), j=0..3, of the CTA's 508-float4
//   chunk (127 edges x 16 ch) with __ldcs (read-once, evict-first). Every
//   LDG.128 is a contiguous 512B warp transaction. Thread's channel-quad
//   q = t&3 is constant across j, so exp() accumulates into one float4.
// Reduction: xor-shuffle over lanes sharing q (masks 4,8,16) covers all
//   32 edges of the warp; 4-warp combine through 256B of smem; 16 threads
//   compute one reciprocal per channel.
// Phase 2 (edge ownership, optimal stores):
//   raw x staged in swizzled smem; thread t (= edge t) reads its 16
//   channels back (4 conflict-free LDS.128), scales by rden, and issues
//   16 warp-coalesced STG.32 with __stcs (write-once, evict-first) —
//   128B runs per channel, the best store shape given the 127-stride.
__global__ __launch_bounds__(128) void attention2_denom_kernel(
    const float* __restrict__ x, float* __restrict__ out)
{
    const int r    = blockIdx.x;
    const int b    = blockIdx.y;
    const int t    = threadIdx.x;
    const int warp = t >> 5;
    const int lane = t & 31;

    __shared__ __align__(16) unsigned char v_s[NM1 * CC * 4 + 64]; // 8128B staged x
    __shared__ float4 ws4[4][4];     // per-warp exp sums: ws4[w][q] = ch 4q..4q+3
    __shared__ float4 rden4[4];      // reciprocal denominators, 16 channels

    const float4* __restrict__ src =
        reinterpret_cast<const float4*>(x + ((size_t)b * NRR + (size_t)r * NM1) * CC);

    // ---- Phase 1: coalesced streaming load, exp, stage, accumulate ---------
    float4 acc = make_float4(0.f, 0.f, 0.f, 0.f);
    #pragma unroll
    for (int j = 0; j < 4; j++) {
        int f = t + 128 * j;                 // float4 index in [0, 508)
        if (f < NM1 * 4) {                   // j=3 predicated (t < 124)
            float4 g = __ldcs(src + f);
            acc.x += __expf(g.x);
            acc.y += __expf(g.y);
            acc.z += __expf(g.z);
            acc.w += __expf(g.w);
            *reinterpret_cast<float4*>(v_s + swz((unsigned)(16 * f))) = g;
        }
    }

    // ---- Reduce over edges: lanes with equal q = t&3 (masks 4,8,16) --------
    #pragma unroll
    for (int m = 4; m <= 16; m <<= 1) {
        acc.x += __shfl_xor_sync(0xffffffffu, acc.x, m);
        acc.y += __shfl_xor_sync(0xffffffffu, acc.y, m);
        acc.z += __shfl_xor_sync(0xffffffffu, acc.z, m);
        acc.w += __shfl_xor_sync(0xffffffffu, acc.w, m);
    }
    if (lane < 4) ws4[warp][lane] = acc;     // lane == its quad q
    __syncthreads();

    if (t < CC) {
        const float* wsf = reinterpret_cast<const float*>(ws4);
        float d = wsf[0 * CC + t] + wsf[1 * CC + t]
                + wsf[2 * CC + t] + wsf[3 * CC + t];
        reinterpret_cast<float*>(rden4)[t] = __frcp_rn(d);
    }
    __syncthreads();

    // ---- Phase 2: edge-owned readback + coalesced streaming stores ---------
    if (t < NM1) {
        float4 rd0 = rden4[0], rd1 = rden4[1], rd2 = rden4[2], rd3 = rden4[3];
        float4 v0 = *reinterpret_cast<const float4*>(v_s + swz((unsigned)(16 * (4 * t + 0))));
        float4 v1 = *reinterpret_cast<const float4*>(v_s + swz((unsigned)(16 * (4 * t + 1))));
        float4 v2 = *reinterpret_cast<const float4*>(v_s + swz((unsigned)(16 * (4 * t + 2))));
        float4 v3 = *reinterpret_cast<const float4*>(v_s + swz((unsigned)(16 * (4 * t + 3))));

        float* o = out + (size_t)b * CC * NRR + (size_t)r * NM1 + (size_t)t;
        __stcs(o +  0 * NRR, v0.x * rd0.x);  __stcs(o +  1 * NRR, v0.y * rd0.y);
        __stcs(o +  2 * NRR, v0.z * rd0.z);  __stcs(o +  3 * NRR, v0.w * rd0.w);
        __stcs(o +  4 * NRR, v1.x * rd1.x);  __stcs(o +  5 * NRR, v1.y * rd1.y);
        __stcs(o +  6 * NRR, v1.z * rd1.z);  __stcs(o +  7 * NRR, v1.w * rd1.w);
        __stcs(o +  8 * NRR, v2.x * rd2.x);  __stcs(o +  9 * NRR, v2.y * rd2.y);
        __stcs(o + 10 * NRR, v2.z * rd2.z);  __stcs(o + 11 * NRR, v2.w * rd2.w);
        __stcs(o + 12 * NRR, v3.x * rd3.x);  __stcs(o + 13 * NRR, v3.y * rd3.y);
        __stcs(o + 14 * NRR, v3.z * rd3.z);  __stcs(o + 15 * NRR, v3.w * rd3.w);
    }
}

extern "C" void kernel_launch(void* const* d_in, const int* in_sizes, int n_in,
                              void* d_out, int out_size)
{
    // d_in[0]: x  float32 [B, NR, C]
    // d_in[1]: receivers int32 [NR] — structurally i/(N-1), unused
    const float* x   = (const float*)d_in[0];
    float*       out = (float*)d_out;   // float32 [B, C, NR]

    dim3 grid(NNODE, BB);   // (receiver, batch)
    attention2_denom_kernel<<<grid, 128>>>(x, out);
}